// round 16
// baseline (speedup 1.0000x reference)
#include <cuda_runtime.h>
#include <math.h>

// Problem constants
#define Bb   64
#define Ss   512
#define Ee   512
#define Hh   1024
#define G4   4096
#define NCOLG 32        // column groups of 128 columns (4096/128)
#define KCHUNK 128      // K elements per item
#define KSPLIT1 12      // 1536 / 128
#define KSPLIT2 16      // 2048 / 128
#define TKT  16         // k-tile staged in shared
#define NBLK 256        // persistent grid (2 CTAs/SM guaranteed co-resident)
#define NTHR 128

// ---------------- scratch (__device__ globals; no allocations) --------------
__device__ float g_X[Ss * Bb * Ee];          // 64 MB  gathered embeddings [t][b][e]
__device__ float g_h1[Bb * Hh];
__device__ float g_c1[Bb * Hh];
__device__ float g_h2[Bb * Hh];
__device__ float g_c2[Bb * Hh];
__device__ float g_zpart[16 * Bb * G4];      // 16 MB  K-split partial sums
__device__ __align__(16) float g_s1[Bb * 8]; // LN1 partial stats [b][q][{sum,sq}]
__device__ __align__(16) float g_s2[Bb * 8]; // LN2 partial stats
__device__ unsigned g_cnt;                   // grid-barrier monotonic counter

typedef unsigned long long ull;

// packed fp32x2 helpers (FFMA2: 2x fp32 rate on sm_103a)
__device__ __forceinline__ ull splat2(float x) {
    ull r; unsigned u = __float_as_uint(x);
    asm("mov.b64 %0, {%1, %1};" : "=l"(r) : "r"(u));
    return r;
}
__device__ __forceinline__ void ffma2(ull& d, ull a, ull b) {
    asm("fma.rn.f32x2 %0, %1, %2, %0;" : "+l"(d) : "l"(a), "l"(b));
}
__device__ __forceinline__ float sigmoidf_(float x) { return 1.0f / (1.0f + expf(-x)); }

// ---------------- grid barrier (monotonic counter, release/acquire) ---------
__device__ __forceinline__ void gridbar(unsigned& target) {
    __syncthreads();
    if (threadIdx.x == 0) {
        __threadfence();                      // release this block's writes
        atomicAdd(&g_cnt, 1u);
        while (*(volatile unsigned*)&g_cnt < target) { }
        __threadfence();                      // acquire others' writes
    }
    __syncthreads();
    target += NBLK;
}

// ---------------- one-time kernels ------------------------------------------
__global__ void gather_kernel(const int* __restrict__ src, const float* __restrict__ emb) {
    int idx = blockIdx.x * 256 + threadIdx.x;      // 0 .. 16777215
    int tt  = idx >> 15;                            // / (B*E = 32768)
    int rem = idx & 32767;
    int b   = rem >> 9;                             // / 512
    int e   = rem & 511;
    int v   = src[b * Ss + tt];
    g_X[idx] = emb[(size_t)v * Ee + e];
}

__global__ void zero_kernel() {
    int idx = blockIdx.x * 256 + threadIdx.x;       // 0 .. 65535
    g_h1[idx] = 0.f; g_c1[idx] = 0.f;
    g_h2[idx] = 0.f; g_c2[idx] = 0.f;
    if (idx == 0) g_cnt = 0u;
}

// ---------------- GEMM item: zpart[ks][64,128cols] = A[64,128k] * W ----------
// Identical inner loop to the validated round-10 kernel; item index replaces
// blockIdx. For LAYER==2, first-half A (= LN1(h1)) is computed on the fly.
template <int LAYER>
__device__ __forceinline__ void gemm_item(
    int it, int t,
    const float* __restrict__ Wx, const float* __restrict__ Wh,
    const float* __restrict__ gl1, const float* __restrict__ bl1,
    float (*As)[68], float (*Ws)[128],
    const float* lnm, const float* lnr)
{
    constexpr int KX = (LAYER == 1) ? Ee : Hh;

    const int cg    = it & (NCOLG - 1);
    const int ks    = it >> 5;
    const int kbase = ks * KCHUNK;
    const int cbase = cg * 128;
    const bool first = (kbase < KX);
    const float* W = first ? (Wx + (size_t)kbase * G4)
                           : (Wh + (size_t)(kbase - KX) * G4);

    const int tid = threadIdx.x;
    const int r0  = (tid >> 4) * 8;
    const int c0a = (tid & 15) * 4;

    ull acc[8][4];
#pragma unroll
    for (int i = 0; i < 8; i++)
#pragma unroll
        for (int j = 0; j < 4; j++) acc[i][j] = 0ull;

    for (int kt = 0; kt < KCHUNK; kt += TKT) {
#pragma unroll
        for (int it8 = 0; it8 < 8; it8++) {          // 16x64 A tile
            int i = it8 * 128 + tid;
            int r = i >> 4, k = i & 15;
            int kidx = kbase + kt + k;
            float a;
            if (LAYER == 1) {
                if (first) a = g_X[(size_t)t * (Bb * Ee) + r * Ee + kidx];
                else       a = __ldcg(&g_h1[r * Hh + (kidx - KX)]);
            } else {
                if (first) {
                    float h = __ldcg(&g_h1[r * Hh + kidx]);
                    a = (h - lnm[r]) * lnr[r] * gl1[kidx] + bl1[kidx];
                } else {
                    a = __ldcg(&g_h2[r * Hh + (kidx - KX)]);
                }
            }
            As[k][r] = a;
        }
#pragma unroll
        for (int i2 = 0; i2 < TKT; i2++)             // 16x128 W tile (read-only, L1)
            Ws[i2][tid] = W[(size_t)(kt + i2) * G4 + cbase + tid];
        __syncthreads();

#pragma unroll
        for (int kk = 0; kk < TKT; kk++) {
            float4 a0 = *(const float4*)&As[kk][r0];
            float4 a1 = *(const float4*)&As[kk][r0 + 4];
            ulonglong2 wA = *(const ulonglong2*)&Ws[kk][c0a];
            ulonglong2 wB = *(const ulonglong2*)&Ws[kk][c0a + 64];
            ull ap[8] = { splat2(a0.x), splat2(a0.y), splat2(a0.z), splat2(a0.w),
                          splat2(a1.x), splat2(a1.y), splat2(a1.z), splat2(a1.w) };
#pragma unroll
            for (int ri = 0; ri < 8; ri++) {
                ffma2(acc[ri][0], ap[ri], wA.x);
                ffma2(acc[ri][1], ap[ri], wA.y);
                ffma2(acc[ri][2], ap[ri], wB.x);
                ffma2(acc[ri][3], ap[ri], wB.y);
            }
        }
        __syncthreads();
    }

#pragma unroll
    for (int ri = 0; ri < 8; ri++) {
        int r = r0 + ri;
        ull* dstA = (ull*)&g_zpart[((size_t)ks * Bb + r) * G4 + cbase + c0a];
        dstA[0] = acc[ri][0]; dstA[1] = acc[ri][1];
        ull* dstB = (ull*)&g_zpart[((size_t)ks * Bb + r) * G4 + cbase + c0a + 64];
        dstB[0] = acc[ri][2]; dstB[1] = acc[ri][3];
    }
}

// ---------------- cell item: block (b, q) handles j in [q*256, q*256+256) ---
// Combines K-split partials + bias, gates, c/h update, writes per-quarter LN
// partial stats (deterministic, no atomics).
template <int KS, int LAYER>
__device__ __forceinline__ void cell_item(const float* __restrict__ bias, float* red)
{
    const int bid = blockIdx.x;
    const int b = bid >> 2, q = bid & 3;
    const int tid = threadIdx.x;
    float* cst = (LAYER == 2) ? g_c2 : g_c1;
    float* hst = (LAYER == 2) ? g_h2 : g_h1;

    float sum = 0.f, sq = 0.f;
#pragma unroll
    for (int jj = 0; jj < 2; jj++) {
        int j = q * 256 + jj * 128 + tid;
        float zi = bias[j], zf = bias[Hh + j], zo = bias[2 * Hh + j], zg = bias[3 * Hh + j];
#pragma unroll
        for (int p = 0; p < KS; p++) {
            const float* zp = g_zpart + ((size_t)p * Bb + b) * G4;
            zi += __ldcg(zp + j);
            zf += __ldcg(zp + Hh + j);
            zo += __ldcg(zp + 2 * Hh + j);
            zg += __ldcg(zp + 3 * Hh + j);
        }
        float ig = sigmoidf_(zi), fg = sigmoidf_(zf), og = sigmoidf_(zo);
        float gg = tanhf(zg);
        float c  = fg * cst[b * Hh + j] + ig * gg;   // own-block data: plain ld fine
        float h  = og * tanhf(c);
        cst[b * Hh + j] = c;
        hst[b * Hh + j] = h;
        sum += h; sq += h * h;
    }
#pragma unroll
    for (int o = 16; o > 0; o >>= 1) {
        sum += __shfl_xor_sync(0xffffffffu, sum, o);
        sq  += __shfl_xor_sync(0xffffffffu, sq,  o);
    }
    int w = tid >> 5, lane = tid & 31;
    if (lane == 0) { red[w] = sum; red[4 + w] = sq; }
    __syncthreads();
    if (tid == 0) {
        float s  = red[0] + red[1] + red[2] + red[3];
        float qq = red[4] + red[5] + red[6] + red[7];
        float* gs = (LAYER == 2) ? g_s2 : g_s1;
        gs[(b * 4 + q) * 2]     = s;
        gs[(b * 4 + q) * 2 + 1] = qq;
    }
    __syncthreads();
}

// ---------------- LN2 + final_outputs row write ------------------------------
__device__ __forceinline__ void outwrite(int row, int t, float* __restrict__ out,
                                         const float* __restrict__ gl2,
                                         const float* __restrict__ bl2)
{
    const int tid = threadIdx.x;
    float4 a  = __ldcg((const float4*)&g_s2[row * 8]);
    float4 b4 = __ldcg((const float4*)&g_s2[row * 8 + 4]);
    float s  = a.x + a.z + b4.x + b4.z;
    float qq = a.y + a.w + b4.y + b4.w;
    float m  = s * (1.0f / Hh);
    float v  = qq * (1.0f / Hh) - m * m;
    float rs = rsqrtf(v + 1e-5f);
    float* orow = out + (size_t)row * (Ss * Hh) + (size_t)t * Hh;
    for (int j = tid; j < Hh; j += NTHR)
        orow[j] = (__ldcg(&g_h2[row * Hh + j]) - m) * rs * gl2[j] + bl2[j];
}

// ---------------- persistent kernel -----------------------------------------
__global__ void __launch_bounds__(NTHR, 2)
persist_kernel(const float* __restrict__ Wx1, const float* __restrict__ Wh1,
               const float* __restrict__ b1,
               const float* __restrict__ Wx2, const float* __restrict__ Wh2,
               const float* __restrict__ b2,
               const float* __restrict__ gl1, const float* __restrict__ bl1,
               const float* __restrict__ gl2, const float* __restrict__ bl2,
               float* __restrict__ out)
{
    __shared__ float As[TKT][68];
    __shared__ float Ws[TKT][128];
    __shared__ float lnm[64], lnr[64];
    __shared__ float red[8];

    const int bid = blockIdx.x;
    unsigned target = NBLK;

    for (int t = 0; t < Ss; t++) {
        // phase 1: gemm layer-1 (+ out row write for t-1 on blocks 192..255)
        for (int it = bid; it < NCOLG * KSPLIT1; it += NBLK)
            gemm_item<1>(it, t, Wx1, Wh1, gl1, bl1, As, Ws, lnm, lnr);
        if (bid >= 192 && t > 0) outwrite(bid - 192, t - 1, out, gl2, bl2);
        gridbar(target);

        // phase 2: cell layer-1 (gates, c1/h1, LN1 partial stats)
        cell_item<KSPLIT1, 1>(b1, red);
        gridbar(target);

        // phase 3: LN1 row params -> smem, then gemm layer-2 (LN1 fused in A)
        if (threadIdx.x < 64) {
            float4 a  = __ldcg((const float4*)&g_s1[threadIdx.x * 8]);
            float4 b4 = __ldcg((const float4*)&g_s1[threadIdx.x * 8 + 4]);
            float s  = a.x + a.z + b4.x + b4.z;
            float qq = a.y + a.w + b4.y + b4.w;
            float m  = s * (1.0f / Hh);
            float v  = qq * (1.0f / Hh) - m * m;
            lnm[threadIdx.x] = m;
            lnr[threadIdx.x] = rsqrtf(v + 1e-5f);
        }
        __syncthreads();
        for (int it = bid; it < NCOLG * KSPLIT2; it += NBLK)
            gemm_item<2>(it, t, Wx2, Wh2, gl1, bl1, As, Ws, lnm, lnr);
        gridbar(target);

        // phase 4: cell layer-2 (gates, c2/h2, LN2 partial stats)
        cell_item<KSPLIT2, 2>(b2, red);
        gridbar(target);
    }

    // epilogue: last out row + final_hidden / final_cell concat
    if (bid >= 192) outwrite(bid - 192, Ss - 1, out, gl2, bl2);
    if (bid < Bb) {
        int b = bid;
        for (int j = threadIdx.x; j < 2048; j += NTHR) {
            float hv = (j < Hh) ? __ldcg(&g_h1[b * Hh + j]) : __ldcg(&g_h2[b * Hh + j - Hh]);
            float cv = (j < Hh) ? __ldcg(&g_c1[b * Hh + j]) : __ldcg(&g_c2[b * Hh + j - Hh]);
            out[33554432 + b * 2048 + j]          = hv;
            out[33554432 + 131072 + b * 2048 + j] = cv;
        }
    }
}

// ---------------- entry -----------------------------------------------------
extern "C" void kernel_launch(void* const* d_in, const int* in_sizes, int n_in,
                              void* d_out, int out_size) {
    const int*   src  = (const int*)d_in[0];
    const float* emb  = (const float*)d_in[1];
    const float* Wx1  = (const float*)d_in[2];
    const float* Wh1  = (const float*)d_in[3];
    const float* b1   = (const float*)d_in[4];
    const float* Wx2  = (const float*)d_in[5];
    const float* Wh2  = (const float*)d_in[6];
    const float* b2   = (const float*)d_in[7];
    const float* gln1 = (const float*)d_in[8];
    const float* bln1 = (const float*)d_in[9];
    const float* gln2 = (const float*)d_in[10];
    const float* bln2 = (const float*)d_in[11];
    float* out = (float*)d_out;

    gather_kernel<<<65536, 256>>>(src, emb);   // X = emb[src], [t][b][e]
    zero_kernel<<<256, 256>>>();               // h0 = c0 = 0, barrier counter = 0

    persist_kernel<<<NBLK, NTHR>>>(Wx1, Wh1, b1, Wx2, Wh2, b2,
                                   gln1, bln1, gln2, bln2, out);
}